// round 7
// baseline (speedup 1.0000x reference)
#include <cuda_runtime.h>
#include <math.h>

#define BATCH 256
#define SEQT  512
#define NIN   256
#define HID   256
#define G3    768
#define NLAYER 2
#define NBLK_RECUR 256u

// ---------------- scratch (device globals; no allocation) ----------------
__device__ float g_weff[NLAYER][NIN * G3];        // [l][k][n]  effective input weights
__device__ float g_ueffT[NLAYER][G3 * HID];       // [l][n][k]  effective recurrent weights, transposed
__device__ float g_wx[SEQT * BATCH * G3];         // [t][b][768] input projections (reused per layer)
__device__ float g_x1[BATCH * SEQT * HID];        // layer-0 output sequence
__device__ float g_hst[2][BATCH * HID];           // double-buffered hidden state
__device__ unsigned int g_bar_count = 0;
__device__ volatile unsigned int g_bar_gen = 0;

// ---------------- effective weight precompute ----------------
// One thread per (l, k, n): Weff[l][k][n] and UeffT[l][n][k].
__global__ void eff_weights_kernel(const float* __restrict__ Wd, const float* __restrict__ Wdg,
                                   const float* __restrict__ Wo, const float* __restrict__ Wog,
                                   const float* __restrict__ Ud, const float* __restrict__ Udg,
                                   const float* __restrict__ Uo, const float* __restrict__ Uog)
{
    int idx = blockIdx.x * blockDim.x + threadIdx.x;      // < 2*256*768
    int n = idx % G3;
    int k = (idx / G3) % NIN;
    int l = idx / (G3 * NIN);

    // Weff
    {
        float s = 0.f;
        const float* wd  = Wd  + (l * NIN + k) * 64;
        const float* wdg = Wdg + l * 64 * G3 + n;
        #pragma unroll 8
        for (int r = 0; r < 64; r++) s = fmaf(wd[r], wdg[r * G3], s);
        const float* wo  = Wo  + (l * NIN + k) * 32;
        const float* wog = Wog + l * 32 * G3 + n;
        #pragma unroll 8
        for (int r = 0; r < 32; r++) s = fmaf(wo[r], wog[r * G3], s);
        g_weff[l][k * G3 + n] = s;
    }
    // UeffT (h == NIN so same k range)
    {
        float s = 0.f;
        const float* ud  = Ud  + (l * HID + k) * 64;
        const float* udg = Udg + l * 64 * G3 + n;
        #pragma unroll 8
        for (int r = 0; r < 64; r++) s = fmaf(ud[r], udg[r * G3], s);
        const float* uo  = Uo  + (l * HID + k) * 32;
        const float* uog = Uog + l * 32 * G3 + n;
        #pragma unroll 8
        for (int r = 0; r < 32; r++) s = fmaf(uo[r], uog[r * G3], s);
        g_ueffT[l][n * HID + k] = s;
    }
}

// ---------------- wx GEMM: out[t*B+b][n] = X[m][k] * Weff[k][n] + bias[n] ----------------
// M = 131072 (m = b*T + t), K = 256, N = 768. 128x128 block tile, 8x8 per thread.
#define BM 128
#define BN 128
#define BK 16
__global__ void __launch_bounds__(256) wx_gemm_kernel(const float* __restrict__ X0,
                                                      const float* __restrict__ bias,
                                                      int layer)
{
    __shared__ __align__(16) float As[BK][BM + 4];
    __shared__ __align__(16) float Bs[BK][BN];

    const float* __restrict__ X = (layer == 0) ? X0 : g_x1;
    const float* __restrict__ W = g_weff[layer];

    const int tid = threadIdx.x;
    const int tx = tid & 15;
    const int ty = tid >> 4;
    const int n0 = blockIdx.x * BN;        // 6 tiles
    const int m0 = blockIdx.y * BM;        // 1024 tiles

    float acc[8][8];
    #pragma unroll
    for (int i = 0; i < 8; i++)
        #pragma unroll
        for (int j = 0; j < 8; j++) acc[i][j] = 0.f;

    for (int kc = 0; kc < NIN; kc += BK) {
        // load A (128 rows x 16 k), transpose into As[k][m]
        #pragma unroll
        for (int i = 0; i < 2; i++) {
            int t = tid + i * 256;         // 0..511
            int m = t >> 2;                // 0..127
            int k4 = (t & 3) << 2;         // 0,4,8,12
            float4 v = *(const float4*)(X + (size_t)(m0 + m) * NIN + kc + k4);
            As[k4 + 0][m] = v.x; As[k4 + 1][m] = v.y;
            As[k4 + 2][m] = v.z; As[k4 + 3][m] = v.w;
        }
        // load B (16 k x 128 n)
        #pragma unroll
        for (int i = 0; i < 2; i++) {
            int t = tid + i * 256;
            int k = t >> 5;                // 0..15
            int n4 = (t & 31) << 2;        // 0..124
            *(float4*)&Bs[k][n4] = *(const float4*)(W + (size_t)(kc + k) * G3 + n0 + n4);
        }
        __syncthreads();
        #pragma unroll
        for (int kk = 0; kk < BK; kk++) {
            float a[8], b[8];
            *(float4*)&a[0] = *(const float4*)&As[kk][ty * 4];
            *(float4*)&a[4] = *(const float4*)&As[kk][64 + ty * 4];
            *(float4*)&b[0] = *(const float4*)&Bs[kk][tx * 4];
            *(float4*)&b[4] = *(const float4*)&Bs[kk][64 + tx * 4];
            #pragma unroll
            for (int i = 0; i < 8; i++)
                #pragma unroll
                for (int j = 0; j < 8; j++) acc[i][j] = fmaf(a[i], b[j], acc[i][j]);
        }
        __syncthreads();
    }

    float bv[8];
    #pragma unroll
    for (int j = 0; j < 8; j++) {
        int n = n0 + ((j < 4) ? tx * 4 + j : 64 + tx * 4 + (j - 4));
        bv[j] = bias[n];
    }
    #pragma unroll
    for (int i = 0; i < 8; i++) {
        int m = m0 + ((i < 4) ? ty * 4 + i : 64 + ty * 4 + (i - 4));
        int bidx = m >> 9;            // /T
        int tt   = m & 511;           // %T
        float* orow = g_wx + ((size_t)tt * BATCH + bidx) * G3 + n0;
        float4 v0 = make_float4(acc[i][0] + bv[0], acc[i][1] + bv[1],
                                acc[i][2] + bv[2], acc[i][3] + bv[3]);
        float4 v1 = make_float4(acc[i][4] + bv[4], acc[i][5] + bv[5],
                                acc[i][6] + bv[6], acc[i][7] + bv[7]);
        *(float4*)(orow + tx * 4) = v0;
        *(float4*)(orow + 64 + tx * 4) = v1;
    }
}

// ---------------- grid barrier (all blocks guaranteed co-resident) ----------------
__device__ __forceinline__ void grid_barrier(unsigned int nb)
{
    __syncthreads();
    if (threadIdx.x == 0) {
        __threadfence();
        unsigned int g = g_bar_gen;
        unsigned int old = atomicAdd(&g_bar_count, 1u);
        if (old == nb - 1u) {
            g_bar_count = 0u;
            __threadfence();
            g_bar_gen = g + 1u;
        } else {
            while (g_bar_gen == g) { __nanosleep(40); }
        }
        __threadfence();
    }
    __syncthreads();
}

#define DOT4(acc, hv, up, kk) do { \
    float4 u_ = *(const float4*)&(up)[kk]; \
    acc = fmaf((hv).x, u_.x, acc); acc = fmaf((hv).y, u_.y, acc); \
    acc = fmaf((hv).z, u_.z, acc); acc = fmaf((hv).w, u_.w, acc); } while (0)

// ---------------- persistent recurrence kernel ----------------
// grid (8, 32): blockIdx.x -> 32 batch rows, blockIdx.y -> 8 hidden cols.
// 128 threads = 4 warps; warp w handles j0 = j_base + 2w, j1 = j0+1 for all 32 b (lane = b).
// Ueff^T tile (24 rows x 256) resident in smem; h chunks (32x64) double-buffered per step.
__global__ void __launch_bounds__(128, 2) recur_kernel(float* __restrict__ out, int layer)
{
    __shared__ __align__(16) float su[24][260];
    __shared__ __align__(16) float sh[2][32][68];

    const int tid = threadIdx.x;
    const int lane = tid & 31;
    const int w = tid >> 5;
    const int b_base = blockIdx.x << 5;
    const int j_base = blockIdx.y << 3;
    const int b = b_base + lane;

    const float* __restrict__ uT = g_ueffT[layer];
    float* __restrict__ xout = layer ? out : g_x1;
    float* __restrict__ hout = out + (size_t)BATCH * SEQT * HID;

    // load U tile once: 24 rows (3 gates x 8 j) x 256 k
    for (int q = tid; q < 24 * 64; q += 128) {
        int row = q >> 6;
        int c4 = (q & 63) << 2;
        int g = row >> 3, jl = row & 7;
        *(float4*)&su[row][c4] = *(const float4*)(uT + ((size_t)((g << 8) + j_base + jl)) * HID + c4);
    }

    // zero init both h buffers for this block's (b,j) region
    #pragma unroll
    for (int i = 0; i < 2; i++) {
        int idx = tid + (i << 7);      // 0..255
        int bb = idx >> 3, jj = idx & 7;
        g_hst[0][(b_base + bb) * HID + j_base + jj] = 0.f;
        g_hst[1][(b_base + bb) * HID + j_base + jj] = 0.f;
    }
    grid_barrier(NBLK_RECUR);

    const int j0 = j_base + (w << 1);
    int p = 0;

    for (int t = 0; t < SEQT; t++) {
        const float* __restrict__ hbuf = g_hst[p];
        float* __restrict__ hw = g_hst[p ^ 1];
        float az0 = 0.f, ar0 = 0.f, ac0 = 0.f, az1 = 0.f, ar1 = 0.f, ac1 = 0.f;

        float4 rh[4];
        // prologue: load h chunk 0 (32 rows x 64 cols)
        #pragma unroll
        for (int i = 0; i < 4; i++) {
            int q = tid + (i << 7);    // 0..511
            int row = q >> 4; int c4 = (q & 15) << 2;
            rh[i] = *(const float4*)(hbuf + (b_base + row) * HID + c4);
        }
        #pragma unroll
        for (int i = 0; i < 4; i++) {
            int q = tid + (i << 7);
            int row = q >> 4; int c4 = (q & 15) << 2;
            *(float4*)&sh[0][row][c4] = rh[i];
        }
        __syncthreads();

        #pragma unroll
        for (int kc = 0; kc < 4; kc++) {
            const int cur = kc & 1;
            if (kc < 3) {
                #pragma unroll
                for (int i = 0; i < 4; i++) {
                    int q = tid + (i << 7);
                    int row = q >> 4; int c4 = (q & 15) << 2;
                    rh[i] = *(const float4*)(hbuf + (b_base + row) * HID + ((kc + 1) << 6) + c4);
                }
            }
            const int kb = kc << 6;
            const float* uzp0 = &su[(w << 1)][kb];
            const float* uzp1 = &su[(w << 1) + 1][kb];
            const float* urp0 = &su[8 + (w << 1)][kb];
            const float* urp1 = &su[8 + (w << 1) + 1][kb];
            const float* ucp0 = &su[16 + (w << 1)][kb];
            const float* ucp1 = &su[16 + (w << 1) + 1][kb];
            const float* hr = &sh[cur][lane][0];
            #pragma unroll
            for (int kk = 0; kk < 64; kk += 4) {
                float4 hv = *(const float4*)&hr[kk];
                DOT4(az0, hv, uzp0, kk);
                DOT4(ar0, hv, urp0, kk);
                DOT4(ac0, hv, ucp0, kk);
                DOT4(az1, hv, uzp1, kk);
                DOT4(ar1, hv, urp1, kk);
                DOT4(ac1, hv, ucp1, kk);
            }
            if (kc < 3) {
                #pragma unroll
                for (int i = 0; i < 4; i++) {
                    int q = tid + (i << 7);
                    int row = q >> 4; int c4 = (q & 15) << 2;
                    *(float4*)&sh[cur ^ 1][row][c4] = rh[i];
                }
            }
            __syncthreads();
        }

        // gate math (j0, j0+1 adjacent -> float2 traffic)
        const float* wrow = g_wx + ((size_t)t * BATCH + b) * G3;
        float2 wz = *(const float2*)&wrow[j0];
        float2 wr = *(const float2*)&wrow[HID + j0];
        float2 wc = *(const float2*)&wrow[2 * HID + j0];
        float2 hp = *(const float2*)&hbuf[b * HID + j0];

        float z0 = 1.f / (1.f + expf(-(wz.x + az0)));
        float r0 = 1.f / (1.f + expf(-(wr.x + ar0)));
        float c0 = tanhf(wc.x + r0 * ac0);
        float hn0 = z0 * hp.x + (1.f - z0) * c0;

        float z1 = 1.f / (1.f + expf(-(wz.y + az1)));
        float r1 = 1.f / (1.f + expf(-(wr.y + ar1)));
        float c1 = tanhf(wc.y + r1 * ac1);
        float hn1 = z1 * hp.y + (1.f - z1) * c1;

        float2 hn = make_float2(hn0, hn1);
        *(float2*)&hw[b * HID + j0] = hn;
        *(float2*)&xout[((size_t)b * SEQT + t) * HID + j0] = hn;
        if (t == SEQT - 1)
            *(float2*)&hout[b * (NLAYER * HID) + layer * HID + j0] = hn;

        grid_barrier(NBLK_RECUR);
        p ^= 1;
    }
}

// ---------------- launch ----------------
extern "C" void kernel_launch(void* const* d_in, const int* in_sizes, int n_in,
                              void* d_out, int out_size)
{
    const float* x   = (const float*)d_in[0];
    const float* Wd  = (const float*)d_in[1];
    const float* Wdg = (const float*)d_in[2];
    const float* Wo  = (const float*)d_in[3];
    const float* Wog = (const float*)d_in[4];
    const float* Ud  = (const float*)d_in[5];
    const float* Udg = (const float*)d_in[6];
    const float* Uo  = (const float*)d_in[7];
    const float* Uog = (const float*)d_in[8];
    const float* bb  = (const float*)d_in[9];
    float* out = (float*)d_out;

    eff_weights_kernel<<<(NLAYER * NIN * G3) / 256, 256>>>(Wd, Wdg, Wo, Wog, Ud, Udg, Uo, Uog);

    for (int l = 0; l < NLAYER; l++) {
        wx_gemm_kernel<<<dim3(G3 / BN, (BATCH * SEQT) / BM), 256>>>(x, bb + l * G3, l);
        recur_kernel<<<dim3(8, 32), 128>>>(out, l);
    }
}

// round 8
// speedup vs baseline: 1.0982x; 1.0982x over previous
#include <cuda_runtime.h>
#include <math.h>

#define BATCH 256
#define SEQT  512
#define NIN   256
#define HID   256
#define G3    768
#define NLAYER 2
#define MTOT  (BATCH * SEQT)
#define NBLK_RECUR 256u

// ---------------- scratch (device globals; no allocation) ----------------
__device__ float g_weff[NLAYER][NIN * G3];        // [l][k][n]
__device__ float g_ueffT[NLAYER][G3 * HID];       // [l][n][k]
__device__ float g_wx[SEQT * BATCH * G3];         // [t][b][768]
__device__ float g_x1[HID * MTOT];                // layer-0 output, [j][m] (m = b*T+t)
__device__ float g_hst[2][BATCH * HID];           // [p][b][k]
__device__ unsigned int g_bar_count = 0;
__device__ unsigned int g_done_count = 0;

// ---------------- helpers ----------------
__device__ __forceinline__ void cp16(void* smem_dst, const void* gmem_src) {
    unsigned s = (unsigned)__cvta_generic_to_shared(smem_dst);
    asm volatile("cp.async.ca.shared.global [%0], [%1], 16;" :: "r"(s), "l"(gmem_src));
}
__device__ __forceinline__ void cp_commit() { asm volatile("cp.async.commit_group;"); }
template<int N> __device__ __forceinline__ void cp_wait() {
    asm volatile("cp.async.wait_group %0;" :: "n"(N));
}
__device__ __forceinline__ void bar_red() {
    asm volatile("red.release.gpu.add.u32 [%0], 1;" :: "l"(&g_bar_count) : "memory");
}
__device__ __forceinline__ unsigned bar_ld() {
    unsigned v;
    asm volatile("ld.acquire.gpu.u32 %0, [%1];" : "=r"(v) : "l"(&g_bar_count) : "memory");
    return v;
}
__device__ __forceinline__ float sigmoid_f(float x) {
    return __fdividef(1.f, 1.f + __expf(-x));
}
__device__ __forceinline__ float tanh_f(float x) {
    return __fdividef(2.f, 1.f + __expf(-2.f * x)) - 1.f;
}

// ---------------- effective weight precompute ----------------
__global__ void eff_weights_kernel(const float* __restrict__ Wd, const float* __restrict__ Wdg,
                                   const float* __restrict__ Wo, const float* __restrict__ Wog,
                                   const float* __restrict__ Ud, const float* __restrict__ Udg,
                                   const float* __restrict__ Uo, const float* __restrict__ Uog)
{
    int idx = blockIdx.x * blockDim.x + threadIdx.x;
    int n = idx % G3;
    int k = (idx / G3) % NIN;
    int l = idx / (G3 * NIN);
    {
        float s = 0.f;
        const float* wd  = Wd  + (l * NIN + k) * 64;
        const float* wdg = Wdg + l * 64 * G3 + n;
        #pragma unroll 8
        for (int r = 0; r < 64; r++) s = fmaf(wd[r], wdg[r * G3], s);
        const float* wo  = Wo  + (l * NIN + k) * 32;
        const float* wog = Wog + l * 32 * G3 + n;
        #pragma unroll 8
        for (int r = 0; r < 32; r++) s = fmaf(wo[r], wog[r * G3], s);
        g_weff[l][k * G3 + n] = s;
    }
    {
        float s = 0.f;
        const float* ud  = Ud  + (l * HID + k) * 64;
        const float* udg = Udg + l * 64 * G3 + n;
        #pragma unroll 8
        for (int r = 0; r < 64; r++) s = fmaf(ud[r], udg[r * G3], s);
        const float* uo  = Uo  + (l * HID + k) * 32;
        const float* uog = Uog + l * 32 * G3 + n;
        #pragma unroll 8
        for (int r = 0; r < 32; r++) s = fmaf(uo[r], uog[r * G3], s);
        g_ueffT[l][n * HID + k] = s;
    }
}

// ---------------- wx GEMM ----------------
// layer 0: A = X [m][k] row-major (transpose into As)
// layer 1: A = g_x1 [k][m]        (direct float4 copy into As)
#define BM 128
#define BN 128
#define BK 16
__global__ void __launch_bounds__(256) wx_gemm_kernel(const float* __restrict__ X0,
                                                      const float* __restrict__ bias,
                                                      int layer)
{
    __shared__ __align__(16) float As[BK][BM + 4];
    __shared__ __align__(16) float Bs[BK][BN];

    const float* __restrict__ W = g_weff[layer];

    const int tid = threadIdx.x;
    const int tx = tid & 15;
    const int ty = tid >> 4;
    const int n0 = blockIdx.x * BN;
    const int m0 = blockIdx.y * BM;

    float acc[8][8];
    #pragma unroll
    for (int i = 0; i < 8; i++)
        #pragma unroll
        for (int j = 0; j < 8; j++) acc[i][j] = 0.f;

    for (int kc = 0; kc < NIN; kc += BK) {
        if (layer == 0) {
            #pragma unroll
            for (int i = 0; i < 2; i++) {
                int t = tid + i * 256;
                int m = t >> 2;
                int k4 = (t & 3) << 2;
                float4 v = *(const float4*)(X0 + (size_t)(m0 + m) * NIN + kc + k4);
                As[k4 + 0][m] = v.x; As[k4 + 1][m] = v.y;
                As[k4 + 2][m] = v.z; As[k4 + 3][m] = v.w;
            }
        } else {
            #pragma unroll
            for (int i = 0; i < 2; i++) {
                int t = tid + i * 256;
                int k = t >> 5;
                int m4 = (t & 31) << 2;
                *(float4*)&As[k][m4] = *(const float4*)(g_x1 + (size_t)(kc + k) * MTOT + m0 + m4);
            }
        }
        #pragma unroll
        for (int i = 0; i < 2; i++) {
            int t = tid + i * 256;
            int k = t >> 5;
            int n4 = (t & 31) << 2;
            *(float4*)&Bs[k][n4] = *(const float4*)(W + (size_t)(kc + k) * G3 + n0 + n4);
        }
        __syncthreads();
        #pragma unroll
        for (int kk = 0; kk < BK; kk++) {
            float a[8], b[8];
            *(float4*)&a[0] = *(const float4*)&As[kk][ty * 4];
            *(float4*)&a[4] = *(const float4*)&As[kk][64 + ty * 4];
            *(float4*)&b[0] = *(const float4*)&Bs[kk][tx * 4];
            *(float4*)&b[4] = *(const float4*)&Bs[kk][64 + tx * 4];
            #pragma unroll
            for (int i = 0; i < 8; i++)
                #pragma unroll
                for (int j = 0; j < 8; j++) acc[i][j] = fmaf(a[i], b[j], acc[i][j]);
        }
        __syncthreads();
    }

    float bv[8];
    #pragma unroll
    for (int j = 0; j < 8; j++) {
        int n = n0 + ((j < 4) ? tx * 4 + j : 64 + tx * 4 + (j - 4));
        bv[j] = bias[n];
    }
    #pragma unroll
    for (int i = 0; i < 8; i++) {
        int m = m0 + ((i < 4) ? ty * 4 + i : 64 + ty * 4 + (i - 4));
        int bidx = m >> 9;
        int tt   = m & 511;
        float* orow = g_wx + ((size_t)tt * BATCH + bidx) * G3 + n0;
        float4 v0 = make_float4(acc[i][0] + bv[0], acc[i][1] + bv[1],
                                acc[i][2] + bv[2], acc[i][3] + bv[3]);
        float4 v1 = make_float4(acc[i][4] + bv[4], acc[i][5] + bv[5],
                                acc[i][6] + bv[6], acc[i][7] + bv[7]);
        *(float4*)(orow + tx * 4) = v0;
        *(float4*)(orow + 64 + tx * 4) = v1;
    }
}

#define DOT4(acc, hv, up, kk) do { \
    float4 u_ = *(const float4*)&(up)[kk]; \
    acc = fmaf((hv).x, u_.x, acc); acc = fmaf((hv).y, u_.y, acc); \
    acc = fmaf((hv).z, u_.z, acc); acc = fmaf((hv).w, u_.w, acc); } while (0)

// ---------------- persistent recurrence kernel ----------------
// grid (8, 32): blockIdx.x -> 32 batch rows (b_base), blockIdx.y -> 8 hidden cols (j_base).
// 128 threads = 4 warps; warp w handles j0 = j_base + 2w, j0+1 for all 32 b (lane = b).
__global__ void __launch_bounds__(128, 2) recur_kernel(float* __restrict__ out, int layer)
{
    __shared__ __align__(16) float su[24][260];       // 24960 B
    __shared__ __align__(16) float sh[2][32][68];     // 17408 B

    const int tid = threadIdx.x;
    const int lane = tid & 31;
    const int w = tid >> 5;
    const int b_base = blockIdx.x << 5;
    const int j_base = blockIdx.y << 3;
    const int b = b_base + lane;
    const int j0 = j_base + (w << 1);

    const float* __restrict__ uT = g_ueffT[layer];
    float* __restrict__ hout = out + (size_t)MTOT * HID;

    // load U tile once: 24 rows (3 gates x 8 j) x 256 k
    for (int q = tid; q < 24 * 64; q += 128) {
        int row = q >> 6;
        int c4 = (q & 63) << 2;
        int g = row >> 3, jl = row & 7;
        *(float4*)&su[row][c4] = *(const float4*)(uT + ((size_t)((g << 8) + j_base + jl)) * HID + c4);
    }

    // zero-init g_hst[0] patch owned by this block: 32 b x 8 j
    #pragma unroll
    for (int i = 0; i < 2; i++) {
        int idx = tid + (i << 7);
        int bb = idx >> 3, jj = idx & 7;
        g_hst[0][(b_base + bb) * HID + j_base + jj] = 0.f;
    }

    unsigned barIdx = 0;
    // init barrier
    __threadfence();
    __syncthreads();
    if (tid == 0) {
        bar_red();
        unsigned tgt = (++barIdx) * NBLK_RECUR;
        while (bar_ld() < tgt) {}
    } else barIdx++;
    __syncthreads();

    float hp0 = 0.f, hp1 = 0.f;
    float xb0[8], xb1[8];
    int p = 0;

    for (int t = 0; t < SEQT; t++) {
        const float* __restrict__ hg = g_hst[p];
        float* __restrict__ hw = g_hst[p ^ 1];

        // wx prefetch (independent of h)
        const float* wrow = g_wx + ((size_t)t * BATCH + b) * G3;
        float2 wz = *(const float2*)&wrow[j0];
        float2 wr = *(const float2*)&wrow[HID + j0];
        float2 wc = *(const float2*)&wrow[2 * HID + j0];

        // issue h chunks 0 and 1 via cp.async
        #pragma unroll
        for (int i = 0; i < 4; i++) {
            int e = tid + (i << 7);
            int row = e >> 4, c4 = (e & 15) << 2;
            cp16(&sh[0][row][c4], hg + (b_base + row) * HID + c4);
        }
        cp_commit();
        #pragma unroll
        for (int i = 0; i < 4; i++) {
            int e = tid + (i << 7);
            int row = e >> 4, c4 = (e & 15) << 2;
            cp16(&sh[1][row][c4], hg + (b_base + row) * HID + 64 + c4);
        }
        cp_commit();

        float az0 = 0.f, ar0 = 0.f, ac0 = 0.f, az1 = 0.f, ar1 = 0.f, ac1 = 0.f;

        #pragma unroll
        for (int kc = 0; kc < 4; kc++) {
            if (kc < 3) cp_wait<1>(); else cp_wait<0>();
            __syncthreads();

            const int cur = kc & 1;
            const int kb = kc << 6;
            const float* uzp0 = &su[(w << 1)][kb];
            const float* uzp1 = &su[(w << 1) + 1][kb];
            const float* urp0 = &su[8 + (w << 1)][kb];
            const float* urp1 = &su[8 + (w << 1) + 1][kb];
            const float* ucp0 = &su[16 + (w << 1)][kb];
            const float* ucp1 = &su[16 + (w << 1) + 1][kb];
            const float* hr = &sh[cur][lane][0];
            #pragma unroll
            for (int kk = 0; kk < 64; kk += 4) {
                float4 hv = *(const float4*)&hr[kk];
                DOT4(az0, hv, uzp0, kk);
                DOT4(ar0, hv, urp0, kk);
                DOT4(ac0, hv, ucp0, kk);
                DOT4(az1, hv, uzp1, kk);
                DOT4(ar1, hv, urp1, kk);
                DOT4(ac1, hv, ucp1, kk);
            }

            if (kc < 2) {
                __syncthreads();   // everyone done reading buf(cur) before refill
                #pragma unroll
                for (int i = 0; i < 4; i++) {
                    int e = tid + (i << 7);
                    int row = e >> 4, c4 = (e & 15) << 2;
                    cp16(&sh[cur][row][c4], hg + (b_base + row) * HID + ((kc + 2) << 6) + c4);
                }
                cp_commit();
            }
        }

        // gate math
        float z0 = sigmoid_f(wz.x + az0);
        float r0 = sigmoid_f(wr.x + ar0);
        float c0 = tanh_f(wc.x + r0 * ac0);
        float hn0 = fmaf(z0, hp0 - c0, c0);

        float z1 = sigmoid_f(wz.y + az1);
        float r1 = sigmoid_f(wr.y + ar1);
        float c1 = tanh_f(wc.y + r1 * ac1);
        float hn1 = fmaf(z1, hp1 - c1, c1);

        if (t < SEQT - 1) {
            // h-state store + release + arrive (minimal fence payload)
            *(float2*)&hw[b * HID + j0] = make_float2(hn0, hn1);
            __threadfence();
            __syncthreads();
            if (tid == 0) bar_red();
        }

        // sequence output (consumed only by later kernel launches)
        int ph = t & 7;
        if (layer == 0) {
            xb0[ph] = hn0; xb1[ph] = hn1;
            if (ph == 7) {
                size_t mb = (size_t)b * SEQT + (t - 7);
                float* r0p = g_x1 + (size_t)j0 * MTOT + mb;
                float* r1p = g_x1 + (size_t)(j0 + 1) * MTOT + mb;
                *(float4*)r0p       = make_float4(xb0[0], xb0[1], xb0[2], xb0[3]);
                *(float4*)(r0p + 4) = make_float4(xb0[4], xb0[5], xb0[6], xb0[7]);
                *(float4*)r1p       = make_float4(xb1[0], xb1[1], xb1[2], xb1[3]);
                *(float4*)(r1p + 4) = make_float4(xb1[4], xb1[5], xb1[6], xb1[7]);
            }
        } else {
            *(float2*)&out[((size_t)b * SEQT + t) * HID + j0] = make_float2(hn0, hn1);
        }
        if (t == SEQT - 1)
            *(float2*)&hout[b * (NLAYER * HID) + layer * HID + j0] = make_float2(hn0, hn1);

        if (t < SEQT - 1) {
            if (tid == 0) {
                unsigned tgt = (++barIdx) * NBLK_RECUR;
                while (bar_ld() < tgt) {}
            } else barIdx++;
            __syncthreads();
        }

        hp0 = hn0; hp1 = hn1;
        p ^= 1;
    }

    // ---- end-of-kernel reset protocol (leaves counters at 0 for next launch) ----
    __syncthreads();
    if (tid == 0) {
        __threadfence();
        asm volatile("red.release.gpu.add.u32 [%0], 1;" :: "l"(&g_done_count) : "memory");
        if (blockIdx.x == 0 && blockIdx.y == 0) {
            unsigned v;
            do {
                asm volatile("ld.acquire.gpu.u32 %0, [%1];" : "=r"(v) : "l"(&g_done_count) : "memory");
            } while (v < NBLK_RECUR);
            g_bar_count = 0u;
            g_done_count = 0u;
            __threadfence();
        }
    }
}

// ---------------- launch ----------------
extern "C" void kernel_launch(void* const* d_in, const int* in_sizes, int n_in,
                              void* d_out, int out_size)
{
    const float* x   = (const float*)d_in[0];
    const float* Wd  = (const float*)d_in[1];
    const float* Wdg = (const float*)d_in[2];
    const float* Wo  = (const float*)d_in[3];
    const float* Wog = (const float*)d_in[4];
    const float* Ud  = (const float*)d_in[5];
    const float* Udg = (const float*)d_in[6];
    const float* Uo  = (const float*)d_in[7];
    const float* Uog = (const float*)d_in[8];
    const float* bb  = (const float*)d_in[9];
    float* out = (float*)d_out;

    eff_weights_kernel<<<(NLAYER * NIN * G3) / 256, 256>>>(Wd, Wdg, Wo, Wog, Ud, Udg, Uo, Uog);

    for (int l = 0; l < NLAYER; l++) {
        wx_gemm_kernel<<<dim3(G3 / BN, MTOT / BM), 256>>>(x, bb + l * G3, l);
        recur_kernel<<<dim3(8, 32), 128>>>(out, l);
    }
}